// round 1
// baseline (speedup 1.0000x reference)
#include <cuda_runtime.h>
#include <cuda_bf16.h>

// C[8192,2048] = A[8192,2048] @ B[2048,2048], fp32.
// A is tile-sparse: ~90% of 64x64 tiles are exactly zero.
// Strategy: kernel 1 scans A and records a per-tile nonzero bitmap in a
// __device__ global; kernel 2 is a classic smem-tiled SIMT fp32 GEMM with
// BM=64 (== sparsity tile) that skips loads+compute for zero k-tiles.

#define M_DIM 8192
#define K_DIM 2048
#define N_DIM 2048
#define TILE 64
#define MT (M_DIM / TILE)   // 128
#define KT (K_DIM / TILE)   // 32

// Per-tile nonzero flags (no device allocation allowed -> __device__ global).
__device__ int g_nz[MT * KT];

// ---------------------------------------------------------------------------
// Kernel 1: scan A, one block per 64x64 tile (4096 blocks x 256 threads).
// ---------------------------------------------------------------------------
__global__ __launch_bounds__(256) void scan_tiles_kernel(const float* __restrict__ A) {
    int tile = blockIdx.x;            // 0..4095
    int tm = tile / KT;               // row-tile
    int tk = tile % KT;               // col-tile
    const float* base = A + (size_t)tm * TILE * K_DIM + tk * TILE;

    bool nz = false;
#pragma unroll
    for (int i = 0; i < 4; i++) {
        int fid = threadIdx.x + 256 * i;   // 0..1023 float4 slots
        int r = fid >> 4;                  // 16 float4 per 64-col row
        int c4 = fid & 15;
        float4 v = *reinterpret_cast<const float4*>(base + (size_t)r * K_DIM + c4 * 4);
        nz |= (v.x != 0.0f) | (v.y != 0.0f) | (v.z != 0.0f) | (v.w != 0.0f);
    }
    int any = __syncthreads_or(nz ? 1 : 0);
    if (threadIdx.x == 0) g_nz[tile] = any;
}

// ---------------------------------------------------------------------------
// Kernel 2: sparse-aware tiled GEMM.
// BM=64, BN=128, BK=64. 128 threads (16 tx x 8 ty), 8x8 outputs per thread.
// ---------------------------------------------------------------------------
#define BM 64
#define BN 128
#define BK 64
#define LDA_S 68   // padded stride for As (float4-aligned: 68*4 % 16 == 0)
#define LDB_S 128

#define SMEM_BYTES ((BM * LDA_S + BK * LDB_S) * 4)

__global__ __launch_bounds__(128) void sparse_gemm_kernel(
    const float* __restrict__ A,
    const float* __restrict__ B,
    float* __restrict__ C)
{
    extern __shared__ float smem[];
    float* As = smem;                 // [BM][LDA_S]  (row-major, m x k)
    float* Bs = smem + BM * LDA_S;    // [BK][LDB_S]  (row-major, k x n)

    const int bn = blockIdx.x;        // 0..15  (N / BN)
    const int bm = blockIdx.y;        // 0..127 (M / BM)
    const int tid = threadIdx.x;
    const int tx = tid & 15;          // 0..15 -> n
    const int ty = tid >> 4;          // 0..7  -> m

    float acc[8][8];
#pragma unroll
    for (int i = 0; i < 8; i++)
#pragma unroll
        for (int j = 0; j < 8; j++) acc[i][j] = 0.0f;

    const float* Abase = A + (size_t)bm * BM * K_DIM;
    const float* Bbase = B + bn * BN;

    for (int kt = 0; kt < KT; kt++) {
        if (!g_nz[bm * KT + kt]) continue;   // uniform across block

        // Load A tile: 64x64 = 1024 float4, 8 per thread.
        const float* Ak = Abase + kt * TILE;
#pragma unroll
        for (int i = 0; i < 8; i++) {
            int fid = tid + 128 * i;         // 0..1023
            int r = fid >> 4;
            int c4 = fid & 15;
            float4 v = *reinterpret_cast<const float4*>(Ak + (size_t)r * K_DIM + c4 * 4);
            *reinterpret_cast<float4*>(&As[r * LDA_S + c4 * 4]) = v;
        }
        // Load B tile: 64x128 = 2048 float4, 16 per thread.
        const float* Bk = Bbase + (size_t)kt * TILE * N_DIM;
#pragma unroll
        for (int i = 0; i < 16; i++) {
            int fid = tid + 128 * i;         // 0..2047
            int r = fid >> 5;                // 32 float4 per 128-col row
            int c4 = fid & 31;
            float4 v = *reinterpret_cast<const float4*>(Bk + (size_t)r * N_DIM + c4 * 4);
            *reinterpret_cast<float4*>(&Bs[r * LDB_S + c4 * 4]) = v;
        }
        __syncthreads();

#pragma unroll 4
        for (int k = 0; k < BK; k++) {
            float a[8], b[8];
#pragma unroll
            for (int i = 0; i < 8; i++) a[i] = As[(ty * 8 + i) * LDA_S + k];
            float4 b0 = *reinterpret_cast<const float4*>(&Bs[k * LDB_S + tx * 8]);
            float4 b1 = *reinterpret_cast<const float4*>(&Bs[k * LDB_S + tx * 8 + 4]);
            b[0] = b0.x; b[1] = b0.y; b[2] = b0.z; b[3] = b0.w;
            b[4] = b1.x; b[5] = b1.y; b[6] = b1.z; b[7] = b1.w;
#pragma unroll
            for (int i = 0; i < 8; i++)
#pragma unroll
                for (int j = 0; j < 8; j++)
                    acc[i][j] = fmaf(a[i], b[j], acc[i][j]);
        }
        __syncthreads();
    }

    // Write C: 8x8 per thread, float4 stores.
    float* Cbase = C + (size_t)(bm * BM) * N_DIM + bn * BN;
#pragma unroll
    for (int i = 0; i < 8; i++) {
        float* crow = Cbase + (size_t)(ty * 8 + i) * N_DIM + tx * 8;
        float4 v0 = make_float4(acc[i][0], acc[i][1], acc[i][2], acc[i][3]);
        float4 v1 = make_float4(acc[i][4], acc[i][5], acc[i][6], acc[i][7]);
        *reinterpret_cast<float4*>(crow) = v0;
        *reinterpret_cast<float4*>(crow + 4) = v1;
    }
}

// ---------------------------------------------------------------------------
extern "C" void kernel_launch(void* const* d_in, const int* in_sizes, int n_in,
                              void* d_out, int out_size)
{
    const float* A = (const float*)d_in[0];   // [8192, 2048]
    const float* B = (const float*)d_in[1];   // [2048, 2048]
    float* C = (float*)d_out;                 // [8192, 2048]

    static bool attr_set = false;
    if (!attr_set) {
        cudaFuncSetAttribute(sparse_gemm_kernel,
                             cudaFuncAttributeMaxDynamicSharedMemorySize,
                             SMEM_BYTES);
        attr_set = true;
    }

    scan_tiles_kernel<<<MT * KT, 256>>>(A);

    dim3 grid(N_DIM / BN, M_DIM / BM);   // (16, 128)
    sparse_gemm_kernel<<<grid, 128, SMEM_BYTES>>>(A, B, C);
}

// round 3
// speedup vs baseline: 1.5347x; 1.5347x over previous
#include <cuda_runtime.h>
#include <cuda_bf16.h>
#include <cstdint>

// C[8192,2048] = A[8192,2048] @ B[2048,2048] fp32; A is 64x64-tile sparse (~90% zero).
// Target is plain sm_100 (no 'a' features) -> tcgen05 unavailable; use mma.sync HMMA.
//   K1: scan A tiles -> g_nz; split-convert nonzero tiles A -> g_Ahi/g_Alo (bf16 + residual)
//   K2: transpose+split-convert B -> g_Bthi/g_Btlo  ([N][K], k-contiguous rows)
//   K3: mma.sync bf16x3 GEMM, BM=128 BN=128 BK=64, 256 thr, 3-stage cp.async pipeline,
//       skipping zero k-slabs. C = Ahi*Bhi + Ahi*Blo + Alo*Bhi (fp32 accum).

#define M_DIM 8192
#define K_DIM 2048
#define N_DIM 2048
#define TS 64
#define MT (M_DIM / TS)     // 128
#define KTN (K_DIM / TS)    // 32

__device__ int g_nz[MT * KTN];
__device__ __nv_bfloat16 g_Ahi[(size_t)M_DIM * K_DIM];   // 32 MB
__device__ __nv_bfloat16 g_Alo[(size_t)M_DIM * K_DIM];   // 32 MB
__device__ __nv_bfloat16 g_Bthi[(size_t)N_DIM * K_DIM];  // 8 MB  [n][k]
__device__ __nv_bfloat16 g_Btlo[(size_t)N_DIM * K_DIM];  // 8 MB  [n][k]

// ---------------------------------------------------------------------------
// helpers
// ---------------------------------------------------------------------------
__device__ __forceinline__ uint32_t smem_to_u32(const void* p) {
    uint32_t a;
    asm("{ .reg .u64 t; cvta.to.shared.u64 t, %1; cvt.u32.u64 %0, t; }"
        : "=r"(a) : "l"(p));
    return a;
}

__device__ __forceinline__ void cp16(uint32_t dst, const void* src) {
    asm volatile("cp.async.cg.shared.global [%0], [%1], 16;"
                 :: "r"(dst), "l"(src) : "memory");
}
#define CP_COMMIT() asm volatile("cp.async.commit_group;" ::: "memory")
#define CP_WAIT(n)  asm volatile("cp.async.wait_group %0;" :: "n"(n) : "memory")

__device__ __forceinline__ void ldmx4(uint32_t* f, uint32_t addr) {
    asm volatile("ldmatrix.sync.aligned.m8n8.x4.shared.b16 {%0,%1,%2,%3}, [%4];"
                 : "=r"(f[0]), "=r"(f[1]), "=r"(f[2]), "=r"(f[3]) : "r"(addr));
}

__device__ __forceinline__ void mma_bf16(float* c, const uint32_t* a, const uint32_t* b) {
    asm volatile(
        "mma.sync.aligned.m16n8k16.row.col.f32.bf16.bf16.f32 "
        "{%0,%1,%2,%3}, {%4,%5,%6,%7}, {%8,%9}, {%0,%1,%2,%3};"
        : "+f"(c[0]), "+f"(c[1]), "+f"(c[2]), "+f"(c[3])
        : "r"(a[0]), "r"(a[1]), "r"(a[2]), "r"(a[3]), "r"(b[0]), "r"(b[1]));
}

__device__ __forceinline__ uint32_t swz(uint32_t bo) {
    return bo ^ ((bo >> 3) & 0x70);
}

__device__ __forceinline__ uint32_t pack_bf16(float a, float b) {
    __nv_bfloat162 h = __floats2bfloat162_rn(a, b);
    return *reinterpret_cast<uint32_t*>(&h);
}

// ---------------------------------------------------------------------------
// K1: scan A tiles; convert+store only nonzero tiles.
// One block per 64x64 tile; 256 threads, 4 float4 each (values kept in regs).
// ---------------------------------------------------------------------------
__global__ __launch_bounds__(256) void scan_convert_a(const float* __restrict__ A) {
    int tile = blockIdx.x;
    int tm = tile / KTN;
    int tk = tile % KTN;
    const float* base = A + (size_t)tm * TS * K_DIM + tk * TS;

    float4 v[4];
    bool nz = false;
#pragma unroll
    for (int i = 0; i < 4; i++) {
        int fid = threadIdx.x + 256 * i;      // 0..1023 float4 slots
        int r = fid >> 4;
        int c4 = fid & 15;
        v[i] = *reinterpret_cast<const float4*>(base + (size_t)r * K_DIM + c4 * 4);
        nz |= (v[i].x != 0.0f) | (v[i].y != 0.0f) | (v[i].z != 0.0f) | (v[i].w != 0.0f);
    }
    int any = __syncthreads_or(nz ? 1 : 0);
    if (threadIdx.x == 0) g_nz[tile] = any;
    if (!any) return;                         // skip stores for zero tiles

#pragma unroll
    for (int i = 0; i < 4; i++) {
        int fid = threadIdx.x + 256 * i;
        int r = fid >> 4;
        int c4 = fid & 15;
        float hx = __bfloat162float(__float2bfloat16_rn(v[i].x));
        float hy = __bfloat162float(__float2bfloat16_rn(v[i].y));
        float hz = __bfloat162float(__float2bfloat16_rn(v[i].z));
        float hw = __bfloat162float(__float2bfloat16_rn(v[i].w));
        size_t gidx = (size_t)(tm * TS + r) * K_DIM + tk * TS + c4 * 4;
        uint2 uh, ul;
        uh.x = pack_bf16(v[i].x, v[i].y);
        uh.y = pack_bf16(v[i].z, v[i].w);
        ul.x = pack_bf16(v[i].x - hx, v[i].y - hy);
        ul.y = pack_bf16(v[i].z - hz, v[i].w - hw);
        *reinterpret_cast<uint2*>(&g_Ahi[gidx]) = uh;
        *reinterpret_cast<uint2*>(&g_Alo[gidx]) = ul;
    }
}

// ---------------------------------------------------------------------------
// K2: transpose + split-convert B[K][N] -> g_Bthi/g_Btlo [N][K]. 64x64 tiles.
// ---------------------------------------------------------------------------
__global__ __launch_bounds__(256) void convert_b_t(const float* __restrict__ B) {
    __shared__ __nv_bfloat16 shi[64][72];   // 144B rows (16B aligned)
    __shared__ __nv_bfloat16 slo[64][72];
    int k0 = blockIdx.x * 64;
    int n0 = blockIdx.y * 64;
    int tid = threadIdx.x;

#pragma unroll
    for (int i = 0; i < 4; i++) {
        int fid = tid + 256 * i;
        int r = fid >> 4;                     // k row within tile
        int c4 = fid & 15;
        float4 v = *reinterpret_cast<const float4*>(B + (size_t)(k0 + r) * N_DIM + n0 + c4 * 4);
        float vv[4] = {v.x, v.y, v.z, v.w};
#pragma unroll
        for (int j = 0; j < 4; j++) {
            int nl = c4 * 4 + j;
            float hv = __bfloat162float(__float2bfloat16_rn(vv[j]));
            shi[nl][r] = __float2bfloat16_rn(vv[j]);
            slo[nl][r] = __float2bfloat16_rn(vv[j] - hv);
        }
    }
    __syncthreads();

#pragma unroll
    for (int i = 0; i < 2; i++) {
        int id = tid + 256 * i;               // 0..511
        int nl = id >> 3;
        int q = id & 7;
        uint4 vh = *reinterpret_cast<const uint4*>(&shi[nl][q * 8]);
        uint4 vl = *reinterpret_cast<const uint4*>(&slo[nl][q * 8]);
        size_t gidx = (size_t)(n0 + nl) * K_DIM + k0 + q * 8;
        *reinterpret_cast<uint4*>(&g_Bthi[gidx]) = vh;
        *reinterpret_cast<uint4*>(&g_Btlo[gidx]) = vl;
    }
}

// ---------------------------------------------------------------------------
// K3: bf16x3 mma.sync GEMM. BM=128 BN=128 BK=64, 256 threads, 3-stage pipeline.
// ---------------------------------------------------------------------------
#define STAGE_BYTES 65536                 // Ahi/Alo/Bhi/Blo @ 16 KB each
#define OFF_ALO 16384
#define OFF_BHI 32768
#define OFF_BLO 49152
#define NSTAGE 3
#define SMEM_CTRL 1024
#define DYN_SMEM (SMEM_CTRL + NSTAGE * STAGE_BYTES)   // 197632

// ldmatrix lane addresses. Tiles stored as 128 rows x 128B (BK=64 bf16), SW128.
__device__ __forceinline__ uint32_t lm_addr_A(uint32_t base, int mBase, int ks, int lane) {
    int g = lane >> 3, r = lane & 7;
    int row = mBase + ((g & 1) << 3) + r;         // g0: m-low klow, g1: m-high klow,
    int col = ks * 32 + ((g >> 1) << 4);          // g2: m-low khigh, g3: m-high khigh
    return base + swz((uint32_t)(row * 128 + col));
}
__device__ __forceinline__ uint32_t lm_addr_B(uint32_t base, int nBase, int ks, int lane) {
    int g = lane >> 3, r = lane & 7;
    int row = nBase + ((g >> 1) << 3) + r;        // g0: n-low klow, g1: n-low khigh,
    int col = ks * 32 + ((g & 1) << 4);           // g2: n-high klow, g3: n-high khigh
    return base + swz((uint32_t)(row * 128 + col));
}

__device__ __forceinline__ void load_stage(uint32_t sbase,
                                           const __nv_bfloat16* Ah, const __nv_bfloat16* Al,
                                           const __nv_bfloat16* Bh, const __nv_bfloat16* Bl,
                                           int tid) {
#pragma unroll
    for (int i = 0; i < 4; i++) {
        int id = tid + 256 * i;                   // 0..1023
        int r = id >> 3;                          // row 0..127
        int seg = id & 7;                         // 16B segment
        uint32_t sw = swz((uint32_t)(r * 128 + seg * 16));
        size_t goff = (size_t)r * K_DIM + seg * 8;
        cp16(sbase + sw,           Ah + goff);
        cp16(sbase + OFF_ALO + sw, Al + goff);
        cp16(sbase + OFF_BHI + sw, Bh + goff);
        cp16(sbase + OFF_BLO + sw, Bl + goff);
    }
}

__global__ __launch_bounds__(256, 1) void sparse_gemm_mma(float* __restrict__ C) {
    extern __shared__ char smem[];
    uint32_t smem_u32 = smem_to_u32(smem) + SMEM_CTRL;
    int tid = threadIdx.x;
    int wid = tid >> 5;
    int lane = tid & 31;
    int wm = wid >> 1;            // 0..3 -> 32-row band
    int wn = wid & 1;             // 0..1 -> 64-col band
    int bn = blockIdx.x;          // 0..15
    int bm = blockIdx.y;          // 0..63
    int gm0 = bm * 128;
    int gn0 = bn * 128;

    // Active k-slab mask (slab = 64 k-cols across both 64-row halves).
    uint32_t mask = 0;
    {
        const int* nz0 = &g_nz[(bm * 2) * KTN];
        const int* nz1 = &g_nz[(bm * 2 + 1) * KTN];
#pragma unroll
        for (int kt = 0; kt < 32; kt++)
            if (nz0[kt] | nz1[kt]) mask |= (1u << kt);
    }

    if (mask == 0) {   // fully zero slab
        float4 z = make_float4(0.f, 0.f, 0.f, 0.f);
        float* crow = C + (size_t)(gm0 + (tid >> 1)) * N_DIM + gn0 + (tid & 1) * 64;
#pragma unroll
        for (int i = 0; i < 16; i++)
            reinterpret_cast<float4*>(crow)[i] = z;
        return;
    }

    int kts[KTN];
    int n = 0;
    {
        uint32_t rem = mask;
        while (rem) { kts[n++] = __ffs(rem) - 1; rem &= rem - 1; }
    }

    const __nv_bfloat16* Ah0 = g_Ahi + (size_t)gm0 * K_DIM;
    const __nv_bfloat16* Al0 = g_Alo + (size_t)gm0 * K_DIM;
    const __nv_bfloat16* Bh0 = g_Bthi + (size_t)gn0 * K_DIM;
    const __nv_bfloat16* Bl0 = g_Btlo + (size_t)gn0 * K_DIM;

    float acc[2][8][4];
#pragma unroll
    for (int mt = 0; mt < 2; mt++)
#pragma unroll
        for (int nt = 0; nt < 8; nt++)
#pragma unroll
            for (int q = 0; q < 4; q++) acc[mt][nt][q] = 0.0f;

    // Prologue: preload up to 2 stages (always commit 2 groups).
#pragma unroll
    for (int j = 0; j < 2; j++) {
        if (j < n) {
            int kt = kts[j];
            load_stage(smem_u32 + j * STAGE_BYTES,
                       Ah0 + kt * TS, Al0 + kt * TS, Bh0 + kt * TS, Bl0 + kt * TS, tid);
        }
        CP_COMMIT();
    }

    for (int i = 0; i < n; i++) {
        if (i + 2 < n) {
            int kt = kts[i + 2];
            load_stage(smem_u32 + ((i + 2) % NSTAGE) * STAGE_BYTES,
                       Ah0 + kt * TS, Al0 + kt * TS, Bh0 + kt * TS, Bl0 + kt * TS, tid);
        }
        CP_COMMIT();
        CP_WAIT(2);
        __syncthreads();

        uint32_t sb = smem_u32 + (i % NSTAGE) * STAGE_BYTES;
        uint32_t aHi = sb, aLo = sb + OFF_ALO, bHi = sb + OFF_BHI, bLo = sb + OFF_BLO;
#pragma unroll
        for (int ks = 0; ks < 4; ks++) {
            uint32_t ah[2][4], al[2][4], bh[4][4], bl[4][4];
#pragma unroll
            for (int mt = 0; mt < 2; mt++) {
                ldmx4(ah[mt], lm_addr_A(aHi, wm * 32 + mt * 16, ks, lane));
                ldmx4(al[mt], lm_addr_A(aLo, wm * 32 + mt * 16, ks, lane));
            }
#pragma unroll
            for (int ng = 0; ng < 4; ng++) {
                ldmx4(bh[ng], lm_addr_B(bHi, wn * 64 + ng * 16, ks, lane));
                ldmx4(bl[ng], lm_addr_B(bLo, wn * 64 + ng * 16, ks, lane));
            }
#pragma unroll
            for (int mt = 0; mt < 2; mt++)
#pragma unroll
                for (int nt = 0; nt < 8; nt++) {
                    const uint32_t* bhp = &bh[nt >> 1][(nt & 1) * 2];
                    const uint32_t* blp = &bl[nt >> 1][(nt & 1) * 2];
                    mma_bf16(acc[mt][nt], ah[mt], bhp);
                    mma_bf16(acc[mt][nt], ah[mt], blp);
                    mma_bf16(acc[mt][nt], al[mt], bhp);
                }
        }
        __syncthreads();   // done with this stage before it is reloaded
    }

    // Epilogue: fragment layout -> C (row = t/4 [+8], cols = 2*(t%4) within n8 tile).
    float* Cw = C + (size_t)(gm0 + wm * 32) * N_DIM + gn0 + wn * 64;
    int r0 = lane >> 2;
    int c0 = (lane & 3) * 2;
#pragma unroll
    for (int mt = 0; mt < 2; mt++)
#pragma unroll
        for (int nt = 0; nt < 8; nt++) {
            float* p = Cw + (size_t)(mt * 16 + r0) * N_DIM + nt * 8 + c0;
            *reinterpret_cast<float2*>(p) = make_float2(acc[mt][nt][0], acc[mt][nt][1]);
            *reinterpret_cast<float2*>(p + 8 * N_DIM) = make_float2(acc[mt][nt][2], acc[mt][nt][3]);
        }
}

// ---------------------------------------------------------------------------
extern "C" void kernel_launch(void* const* d_in, const int* in_sizes, int n_in,
                              void* d_out, int out_size) {
    const float* A = (const float*)d_in[0];   // [8192, 2048]
    const float* B = (const float*)d_in[1];   // [2048, 2048]
    float* C = (float*)d_out;                 // [8192, 2048]

    static bool attr_set = false;
    if (!attr_set) {
        cudaFuncSetAttribute(sparse_gemm_mma,
                             cudaFuncAttributeMaxDynamicSharedMemorySize, DYN_SMEM);
        attr_set = true;
    }

    scan_convert_a<<<MT * KTN, 256>>>(A);
    convert_b_t<<<dim3(K_DIM / 64, N_DIM / 64), 256>>>(B);
    sparse_gemm_mma<<<dim3(N_DIM / 128, M_DIM / 128), 256, DYN_SMEM>>>(C);
}

// round 4
// speedup vs baseline: 2.3498x; 1.5311x over previous
#include <cuda_runtime.h>
#include <cuda_bf16.h>
#include <cstdint>

// C[8192,2048] = A[8192,2048] @ B[2048,2048] fp32; A is 64x64-tile sparse (~90% zero).
// Plain sm_100 target (no tcgen05) -> mma.sync HMMA bf16x3.
//   K1: scan A tiles -> g_nz; split-convert nonzero tiles -> g_Ahi/g_Alo
//   K2: transpose+split-convert B -> g_Bthi/g_Btlo ([N][K])
//   K3: mma.sync bf16x3 GEMM, BM=64(=sparsity tile) BN=128 BK=64, 256 thr,
//       double-buffered cp.async, 2 CTAs/SM, per-slab skip at p=0.9.

#define M_DIM 8192
#define K_DIM 2048
#define N_DIM 2048
#define TS 64
#define MT (M_DIM / TS)     // 128
#define KTN (K_DIM / TS)    // 32

__device__ int g_nz[MT * KTN];
__device__ __nv_bfloat16 g_Ahi[(size_t)M_DIM * K_DIM];   // 32 MB
__device__ __nv_bfloat16 g_Alo[(size_t)M_DIM * K_DIM];   // 32 MB
__device__ __nv_bfloat16 g_Bthi[(size_t)N_DIM * K_DIM];  // 8 MB  [n][k]
__device__ __nv_bfloat16 g_Btlo[(size_t)N_DIM * K_DIM];  // 8 MB  [n][k]

// ---------------------------------------------------------------------------
__device__ __forceinline__ uint32_t smem_to_u32(const void* p) {
    uint32_t a;
    asm("{ .reg .u64 t; cvta.to.shared.u64 t, %1; cvt.u32.u64 %0, t; }"
        : "=r"(a) : "l"(p));
    return a;
}
__device__ __forceinline__ void cp16(uint32_t dst, const void* src) {
    asm volatile("cp.async.cg.shared.global [%0], [%1], 16;"
                 :: "r"(dst), "l"(src) : "memory");
}
#define CP_COMMIT() asm volatile("cp.async.commit_group;" ::: "memory")
#define CP_WAIT(n)  asm volatile("cp.async.wait_group %0;" :: "n"(n) : "memory")

__device__ __forceinline__ void ldmx4(uint32_t* f, uint32_t addr) {
    asm volatile("ldmatrix.sync.aligned.m8n8.x4.shared.b16 {%0,%1,%2,%3}, [%4];"
                 : "=r"(f[0]), "=r"(f[1]), "=r"(f[2]), "=r"(f[3]) : "r"(addr));
}
__device__ __forceinline__ void mma_bf16(float* c, const uint32_t* a, const uint32_t* b) {
    asm volatile(
        "mma.sync.aligned.m16n8k16.row.col.f32.bf16.bf16.f32 "
        "{%0,%1,%2,%3}, {%4,%5,%6,%7}, {%8,%9}, {%0,%1,%2,%3};"
        : "+f"(c[0]), "+f"(c[1]), "+f"(c[2]), "+f"(c[3])
        : "r"(a[0]), "r"(a[1]), "r"(a[2]), "r"(a[3]), "r"(b[0]), "r"(b[1]));
}
__device__ __forceinline__ uint32_t swz(uint32_t bo) { return bo ^ ((bo >> 3) & 0x70); }
__device__ __forceinline__ uint32_t pack_bf16(float a, float b) {
    __nv_bfloat162 h = __floats2bfloat162_rn(a, b);
    return *reinterpret_cast<uint32_t*>(&h);
}

// ---------------------------------------------------------------------------
// K1: scan + split-convert A (stores skipped for zero tiles).
// ---------------------------------------------------------------------------
__global__ __launch_bounds__(256) void scan_convert_a(const float* __restrict__ A) {
    int tile = blockIdx.x;
    int tm = tile / KTN;
    int tk = tile % KTN;
    const float* base = A + (size_t)tm * TS * K_DIM + tk * TS;

    float4 v[4];
    bool nz = false;
#pragma unroll
    for (int i = 0; i < 4; i++) {
        int fid = threadIdx.x + 256 * i;
        int r = fid >> 4;
        int c4 = fid & 15;
        v[i] = *reinterpret_cast<const float4*>(base + (size_t)r * K_DIM + c4 * 4);
        nz |= (v[i].x != 0.0f) | (v[i].y != 0.0f) | (v[i].z != 0.0f) | (v[i].w != 0.0f);
    }
    int any = __syncthreads_or(nz ? 1 : 0);
    if (threadIdx.x == 0) g_nz[tile] = any;
    if (!any) return;

#pragma unroll
    for (int i = 0; i < 4; i++) {
        int fid = threadIdx.x + 256 * i;
        int r = fid >> 4;
        int c4 = fid & 15;
        float hx = __bfloat162float(__float2bfloat16_rn(v[i].x));
        float hy = __bfloat162float(__float2bfloat16_rn(v[i].y));
        float hz = __bfloat162float(__float2bfloat16_rn(v[i].z));
        float hw = __bfloat162float(__float2bfloat16_rn(v[i].w));
        size_t gidx = (size_t)(tm * TS + r) * K_DIM + tk * TS + c4 * 4;
        uint2 uh, ul;
        uh.x = pack_bf16(v[i].x, v[i].y);
        uh.y = pack_bf16(v[i].z, v[i].w);
        ul.x = pack_bf16(v[i].x - hx, v[i].y - hy);
        ul.y = pack_bf16(v[i].z - hz, v[i].w - hw);
        *reinterpret_cast<uint2*>(&g_Ahi[gidx]) = uh;
        *reinterpret_cast<uint2*>(&g_Alo[gidx]) = ul;
    }
}

// ---------------------------------------------------------------------------
// K2: transpose + split-convert B[K][N] -> [N][K]. 64x64 tiles.
// ---------------------------------------------------------------------------
__global__ __launch_bounds__(256) void convert_b_t(const float* __restrict__ B) {
    __shared__ __nv_bfloat16 shi[64][72];
    __shared__ __nv_bfloat16 slo[64][72];
    int k0 = blockIdx.x * 64;
    int n0 = blockIdx.y * 64;
    int tid = threadIdx.x;

#pragma unroll
    for (int i = 0; i < 4; i++) {
        int fid = tid + 256 * i;
        int r = fid >> 4;
        int c4 = fid & 15;
        float4 v = *reinterpret_cast<const float4*>(B + (size_t)(k0 + r) * N_DIM + n0 + c4 * 4);
        float vv[4] = {v.x, v.y, v.z, v.w};
#pragma unroll
        for (int j = 0; j < 4; j++) {
            int nl = c4 * 4 + j;
            float hv = __bfloat162float(__float2bfloat16_rn(vv[j]));
            shi[nl][r] = __float2bfloat16_rn(vv[j]);
            slo[nl][r] = __float2bfloat16_rn(vv[j] - hv);
        }
    }
    __syncthreads();

#pragma unroll
    for (int i = 0; i < 2; i++) {
        int id = tid + 256 * i;
        int nl = id >> 3;
        int q = id & 7;
        uint4 vh = *reinterpret_cast<const uint4*>(&shi[nl][q * 8]);
        uint4 vl = *reinterpret_cast<const uint4*>(&slo[nl][q * 8]);
        size_t gidx = (size_t)(n0 + nl) * K_DIM + k0 + q * 8;
        *reinterpret_cast<uint4*>(&g_Bthi[gidx]) = vh;
        *reinterpret_cast<uint4*>(&g_Btlo[gidx]) = vl;
    }
}

// ---------------------------------------------------------------------------
// K3: bf16x3 mma.sync GEMM. BM=64 BN=128 BK=64, 256 threads, double buffer.
// Stage: Ahi 8K | Alo 8K | Bhi 16K | Blo 16K = 48 KB.
// ---------------------------------------------------------------------------
#define STAGE_BYTES 49152
#define OFF_ALO 8192
#define OFF_BHI 16384
#define OFF_BLO 32768
#define SMEM_CTRL 1024
#define DYN_SMEM (SMEM_CTRL + 2 * STAGE_BYTES)   // 99328 -> 2 CTAs/SM

// ldmatrix lane addresses; tiles have 128B rows (64 bf16 k), SW128 swizzled.
__device__ __forceinline__ uint32_t lm_addr_A(uint32_t base, int mBase, int ks, int lane) {
    int g = lane >> 3, r = lane & 7;
    int row = mBase + ((g & 1) << 3) + r;
    int col = ks * 32 + ((g >> 1) << 4);
    return base + swz((uint32_t)(row * 128 + col));
}
__device__ __forceinline__ uint32_t lm_addr_B(uint32_t base, int nBase, int ks, int lane) {
    int g = lane >> 3, r = lane & 7;
    int row = nBase + ((g >> 1) << 3) + r;
    int col = ks * 32 + ((g & 1) << 4);
    return base + swz((uint32_t)(row * 128 + col));
}

__device__ __forceinline__ void load_stage(uint32_t sbase,
                                           const __nv_bfloat16* Ah, const __nv_bfloat16* Al,
                                           const __nv_bfloat16* Bh, const __nv_bfloat16* Bl,
                                           int tid) {
    // A tiles: 64 rows x 128B = 512 x 16B each; B tiles: 128 rows x 128B = 1024 x 16B.
#pragma unroll
    for (int i = 0; i < 2; i++) {
        int id = tid + 256 * i;                   // 0..511
        int r = id >> 3;
        int seg = id & 7;
        uint32_t sw = swz((uint32_t)(r * 128 + seg * 16));
        size_t goff = (size_t)r * K_DIM + seg * 8;
        cp16(sbase + sw,           Ah + goff);
        cp16(sbase + OFF_ALO + sw, Al + goff);
    }
#pragma unroll
    for (int i = 0; i < 4; i++) {
        int id = tid + 256 * i;                   // 0..1023
        int r = id >> 3;
        int seg = id & 7;
        uint32_t sw = swz((uint32_t)(r * 128 + seg * 16));
        size_t goff = (size_t)r * K_DIM + seg * 8;
        cp16(sbase + OFF_BHI + sw, Bh + goff);
        cp16(sbase + OFF_BLO + sw, Bl + goff);
    }
}

__global__ __launch_bounds__(256, 2) void sparse_gemm_mma(float* __restrict__ C) {
    extern __shared__ char smem[];
    uint32_t smem_u32 = smem_to_u32(smem) + SMEM_CTRL;
    int tid = threadIdx.x;
    int wid = tid >> 5;
    int lane = tid & 31;
    int wm = wid & 1;             // 0..1 -> 32-row band
    int wn = wid >> 1;            // 0..3 -> 32-col band
    int bn = blockIdx.x;          // 0..15
    int bm = blockIdx.y;          // 0..127
    int gm0 = bm * 64;
    int gn0 = bn * 128;

    // Active k-slab mask: exactly the 64x64 tile mask for this row band.
    uint32_t mask = 0;
    {
        const int* nzr = &g_nz[bm * KTN];
#pragma unroll
        for (int kt = 0; kt < KTN; kt++)
            if (nzr[kt]) mask |= (1u << kt);
    }

    if (mask == 0) {   // fully zero row band
        float4 z = make_float4(0.f, 0.f, 0.f, 0.f);
        float* crow = C + (size_t)(gm0 + (tid >> 2)) * N_DIM + gn0 + (tid & 3) * 32;
#pragma unroll
        for (int i = 0; i < 8; i++)
            reinterpret_cast<float4*>(crow)[i] = z;
        return;
    }

    int kts[KTN];
    int n = 0;
    {
        uint32_t rem = mask;
        while (rem) { kts[n++] = __ffs(rem) - 1; rem &= rem - 1; }
    }

    const __nv_bfloat16* Ah0 = g_Ahi + (size_t)gm0 * K_DIM;
    const __nv_bfloat16* Al0 = g_Alo + (size_t)gm0 * K_DIM;
    const __nv_bfloat16* Bh0 = g_Bthi + (size_t)gn0 * K_DIM;
    const __nv_bfloat16* Bl0 = g_Btlo + (size_t)gn0 * K_DIM;

    float acc[2][4][4];
#pragma unroll
    for (int mt = 0; mt < 2; mt++)
#pragma unroll
        for (int nt = 0; nt < 4; nt++)
#pragma unroll
            for (int q = 0; q < 4; q++) acc[mt][nt][q] = 0.0f;

    {
        int kt = kts[0];
        load_stage(smem_u32, Ah0 + kt * TS, Al0 + kt * TS, Bh0 + kt * TS, Bl0 + kt * TS, tid);
    }
    CP_COMMIT();

    for (int i = 0; i < n; i++) {
        if (i + 1 < n) {
            int kt = kts[i + 1];
            load_stage(smem_u32 + ((i + 1) & 1) * STAGE_BYTES,
                       Ah0 + kt * TS, Al0 + kt * TS, Bh0 + kt * TS, Bl0 + kt * TS, tid);
        }
        CP_COMMIT();
        CP_WAIT(1);          // stage i resident
        __syncthreads();

        uint32_t sb = smem_u32 + (i & 1) * STAGE_BYTES;
        uint32_t aHi = sb, aLo = sb + OFF_ALO, bHi = sb + OFF_BHI, bLo = sb + OFF_BLO;
#pragma unroll
        for (int ks = 0; ks < 4; ks++) {
            uint32_t ah[2][4], al[2][4], bh[2][4], bl[2][4];
#pragma unroll
            for (int mt = 0; mt < 2; mt++) {
                ldmx4(ah[mt], lm_addr_A(aHi, wm * 32 + mt * 16, ks, lane));
                ldmx4(al[mt], lm_addr_A(aLo, wm * 32 + mt * 16, ks, lane));
            }
#pragma unroll
            for (int ng = 0; ng < 2; ng++) {
                ldmx4(bh[ng], lm_addr_B(bHi, wn * 32 + ng * 16, ks, lane));
                ldmx4(bl[ng], lm_addr_B(bLo, wn * 32 + ng * 16, ks, lane));
            }
#pragma unroll
            for (int mt = 0; mt < 2; mt++)
#pragma unroll
                for (int nt = 0; nt < 4; nt++) {
                    const uint32_t* bhp = &bh[nt >> 1][(nt & 1) * 2];
                    const uint32_t* blp = &bl[nt >> 1][(nt & 1) * 2];
                    mma_bf16(acc[mt][nt], ah[mt], bhp);
                    mma_bf16(acc[mt][nt], ah[mt], blp);
                    mma_bf16(acc[mt][nt], al[mt], bhp);
                }
        }
        __syncthreads();     // stage i free for reload
    }

    // Epilogue
    float* Cw = C + (size_t)(gm0 + wm * 32) * N_DIM + gn0 + wn * 32;
    int r0 = lane >> 2;
    int c0 = (lane & 3) * 2;
#pragma unroll
    for (int mt = 0; mt < 2; mt++)
#pragma unroll
        for (int nt = 0; nt < 4; nt++) {
            float* p = Cw + (size_t)(mt * 16 + r0) * N_DIM + nt * 8 + c0;
            *reinterpret_cast<float2*>(p) = make_float2(acc[mt][nt][0], acc[mt][nt][1]);
            *reinterpret_cast<float2*>(p + 8 * N_DIM) = make_float2(acc[mt][nt][2], acc[mt][nt][3]);
        }
}

// ---------------------------------------------------------------------------
extern "C" void kernel_launch(void* const* d_in, const int* in_sizes, int n_in,
                              void* d_out, int out_size) {
    const float* A = (const float*)d_in[0];
    const float* B = (const float*)d_in[1];
    float* C = (float*)d_out;

    static bool attr_set = false;
    if (!attr_set) {
        cudaFuncSetAttribute(sparse_gemm_mma,
                             cudaFuncAttributeMaxDynamicSharedMemorySize, DYN_SMEM);
        attr_set = true;
    }

    scan_convert_a<<<MT * KTN, 256>>>(A);
    convert_b_t<<<dim3(K_DIM / 64, N_DIM / 64), 256>>>(B);
    sparse_gemm_mma<<<dim3(N_DIM / 128, MT), 256, DYN_SMEM>>>(C);
}